// round 11
// baseline (speedup 1.0000x reference)
#include <cuda_runtime.h>
#include <cuda_fp16.h>
#include <math.h>
#include <stdint.h>

// ---------------- static problem config ----------------
#define NQ     13294
#define BATCH  2
#define MROWS  (BATCH * NQ)     // 26588
#define E_     256
#define F_     1024
#define CATN   640              // concat proj width: 256 (v) + 256 (off) + 128 (aw)
#define NHEAD  8
#define HDIM   32
#define NLVL   4
#define NPNT   4
#define EPS    1e-5f

// ---------------- scratch (static device globals; no allocation) ----------------
__device__ float  g_x   [MROWS * E_];    // fp32 residual stream
__device__ __half g_xh  [MROWS * E_];    // fp16 view for GEMM A
__device__ __half g_voa [MROWS * CATN];  // [v | off | aw-logits] fp16
__device__ __half g_samp[MROWS * E_];    // deform output (GEMM A)
__device__ __half g_ffn [MROWS * F_];    // FFN hidden
__device__ __half g_wcat[E_ * CATN];
__device__ float  g_bcat[CATN];
__device__ __half g_wo  [E_ * E_];
__device__ __half g_wf1 [E_ * F_];
__device__ __half g_wf2 [F_ * E_];

__constant__ int c_w[NLVL]     = {100, 50, 25, 13};
__constant__ int c_h[NLVL]     = {100, 50, 25, 13};
__constant__ int c_start[NLVL] = {0, 10000, 12500, 13125};

// ---------------- prep kernels (2 launches total) ----------------
__global__ void src_copy_kernel(const float* __restrict__ src,
                                float* __restrict__ xf, __half* __restrict__ xh, int n) {
    int i = blockIdx.x * blockDim.x + threadIdx.x;
    if (i < n) { float v = src[i]; xf[i] = v; xh[i] = __float2half(v); }
}

#define WCAT_N (E_ * CATN)
#define WO_N   (E_ * E_)
#define WF1_N  (E_ * F_)
#define WF2_N  (F_ * E_)
#define PREP_TOTAL (WCAT_N + WO_N + WF1_N + WF2_N)

__global__ void prep_weights_kernel(
    const float* __restrict__ Wv, const float* __restrict__ Woff, const float* __restrict__ Waw,
    const float* __restrict__ bv, const float* __restrict__ boff, const float* __restrict__ baw,
    const float* __restrict__ Wo, const float* __restrict__ Wf1, const float* __restrict__ Wf2,
    __half* __restrict__ wcat, float* __restrict__ bcat,
    __half* __restrict__ wo, __half* __restrict__ wf1, __half* __restrict__ wf2)
{
    int i = blockIdx.x * blockDim.x + threadIdx.x;
    if (i < WCAT_N) {
        int r = i / CATN, c = i % CATN;
        float v;
        if (c < 256)      v = Wv  [r * 256 + c];
        else if (c < 512) v = Woff[r * 256 + (c - 256)];
        else              v = Waw [r * 128 + (c - 512)];
        wcat[i] = __float2half(v);
    } else if (i < WCAT_N + WO_N) {
        int j = i - WCAT_N;
        wo[j] = __float2half(Wo[j]);
    } else if (i < WCAT_N + WO_N + WF1_N) {
        int j = i - WCAT_N - WO_N;
        wf1[j] = __float2half(Wf1[j]);
    } else if (i < PREP_TOTAL) {
        int j = i - WCAT_N - WO_N - WF1_N;
        wf2[j] = __float2half(Wf2[j]);
    }
    if (i < CATN) {
        bcat[i] = (i < 256) ? bv[i] : (i < 512) ? boff[i - 256] : baw[i - 512];
    }
}

// ---------------- cp.async helpers ----------------
__device__ __forceinline__ void cp_async16(void* smem_dst, const void* gmem_src, bool pred) {
    uint32_t saddr = (uint32_t)__cvta_generic_to_shared(smem_dst);
    int sz = pred ? 16 : 0;
    asm volatile("cp.async.cg.shared.global [%0], [%1], 16, %2;\n"
                 :: "r"(saddr), "l"(gmem_src), "r"(sz));
}
#define CP_COMMIT() asm volatile("cp.async.commit_group;\n" ::: "memory")
#define CP_WAIT1()  asm volatile("cp.async.wait_group 1;\n" ::: "memory")

// ---------------- mma / ldmatrix helpers ----------------
__device__ __forceinline__ void mma_f16(
    float& d0, float& d1, float& d2, float& d3,
    uint32_t a0, uint32_t a1, uint32_t a2, uint32_t a3,
    uint32_t b0, uint32_t b1)
{
    asm volatile(
        "mma.sync.aligned.m16n8k16.row.col.f32.f16.f16.f32 "
        "{%0,%1,%2,%3}, {%4,%5,%6,%7}, {%8,%9}, {%0,%1,%2,%3};"
        : "+f"(d0), "+f"(d1), "+f"(d2), "+f"(d3)
        : "r"(a0), "r"(a1), "r"(a2), "r"(a3), "r"(b0), "r"(b1));
}

__device__ __forceinline__ void ldsm_x4(uint32_t& r0, uint32_t& r1, uint32_t& r2, uint32_t& r3,
                                        const __half* p) {
    uint32_t addr = (uint32_t)__cvta_generic_to_shared(p);
    asm volatile("ldmatrix.sync.aligned.m8n8.x4.shared.b16 {%0,%1,%2,%3}, [%4];"
                 : "=r"(r0), "=r"(r1), "=r"(r2), "=r"(r3) : "r"(addr));
}

__device__ __forceinline__ void ldsm_x4_trans(uint32_t& r0, uint32_t& r1, uint32_t& r2, uint32_t& r3,
                                              const __half* p) {
    uint32_t addr = (uint32_t)__cvta_generic_to_shared(p);
    asm volatile("ldmatrix.sync.aligned.m8n8.x4.trans.shared.b16 {%0,%1,%2,%3}, [%4];"
                 : "=r"(r0), "=r"(r1), "=r"(r2), "=r"(r3) : "r"(addr));
}

// ---------------- FP16 tensor-core GEMM (proj / FFN1) ----------------
#define TBM 128
#define TBN 128
#define TBK 64
#define APADH 72
#define BPADH 136
#define NSTAGE 3
#define AS_STAGE (TBM * APADH)
#define BS_STAGE (TBK * BPADH)
#define GEMM_SMEM_BYTES ((NSTAGE * (AS_STAGE + BS_STAGE)) * 2)   // 107520

__global__ __launch_bounds__(256, 2) void gemm_f16(
    const __half* __restrict__ A, const __half* __restrict__ W,
    const float* __restrict__ bias, __half* __restrict__ Cout,
    int M, int K, int N, int relu)
{
    extern __shared__ __half sm[];
    __half* Asm = sm;
    __half* Bsm = sm + NSTAGE * AS_STAGE;

    const int tid = threadIdx.x;
    const int bm  = blockIdx.y * TBM;
    const int bn  = blockIdx.x * TBN;

    const int row_a = tid >> 1;
    const int col_a = (tid & 1) << 5;
    const int row_b = tid >> 2;
    const int col_b = (tid & 3) << 5;

    const bool a_ok = (bm + row_a) < M;

    const int w    = tid >> 5;
    const int wm   = (w & 1) * 64;
    const int wn   = (w >> 1) * 32;
    const int lane = tid & 31;
    const int gid  = lane >> 2;
    const int tig  = lane & 3;
    const int l16  = lane & 15;
    const int lhi  = (lane >> 4) << 3;

    float acc[4][4][4] = {};

    const int KT = K >> 6;

    const __half* Abase = A + (size_t)(bm + row_a) * K + col_a;
    const __half* Bbase = W + (size_t)row_b * N + bn + col_b;

    __half* asm_dst[NSTAGE];
    __half* bsm_dst[NSTAGE];
    #pragma unroll
    for (int s = 0; s < NSTAGE; s++) {
        asm_dst[s] = Asm + s * AS_STAGE + row_a * APADH + col_a;
        bsm_dst[s] = Bsm + s * BS_STAGE + row_b * BPADH + col_b;
    }

    #pragma unroll
    for (int s = 0; s < NSTAGE - 1; s++) {
        const int k0 = s << 6;
        #pragma unroll
        for (int i = 0; i < 4; i++) {
            cp_async16(asm_dst[s] + i * 8, Abase + k0 + i * 8, a_ok);
            cp_async16(bsm_dst[s] + i * 8, Bbase + (size_t)k0 * N + i * 8, true);
        }
        CP_COMMIT();
    }

    for (int kt = 0; kt < KT; kt++) {
        CP_WAIT1();
        __syncthreads();

        if (kt + NSTAGE - 1 < KT) {
            const int s  = (kt + NSTAGE - 1) % NSTAGE;
            const int k0 = (kt + NSTAGE - 1) << 6;
            #pragma unroll
            for (int i = 0; i < 4; i++) {
                cp_async16(asm_dst[s] + i * 8, Abase + k0 + i * 8, a_ok);
                cp_async16(bsm_dst[s] + i * 8, Bbase + (size_t)k0 * N + i * 8, true);
            }
        }
        CP_COMMIT();

        const __half* Ab = Asm + (kt % NSTAGE) * AS_STAGE;
        const __half* Bb = Bsm + (kt % NSTAGE) * BS_STAGE;

        #pragma unroll
        for (int ks = 0; ks < 4; ks++) {
            const int kk = ks << 4;
            uint32_t af[4][4];
            uint32_t bf[4][2];
            #pragma unroll
            for (int mt = 0; mt < 4; mt++) {
                const int r0 = wm + mt * 16;
                ldsm_x4(af[mt][0], af[mt][1], af[mt][2], af[mt][3],
                        Ab + (size_t)(r0 + l16) * APADH + kk + lhi);
            }
            #pragma unroll
            for (int pr = 0; pr < 2; pr++) {
                const int c0 = wn + pr * 16;
                ldsm_x4_trans(bf[pr * 2][0], bf[pr * 2][1], bf[pr * 2 + 1][0], bf[pr * 2 + 1][1],
                              Bb + (size_t)(kk + l16) * BPADH + c0 + lhi);
            }
            #pragma unroll
            for (int mt = 0; mt < 4; mt++)
                #pragma unroll
                for (int nt = 0; nt < 4; nt++)
                    mma_f16(acc[mt][nt][0], acc[mt][nt][1], acc[mt][nt][2], acc[mt][nt][3],
                            af[mt][0], af[mt][1], af[mt][2], af[mt][3],
                            bf[nt][0], bf[nt][1]);
        }
    }

    #pragma unroll
    for (int mt = 0; mt < 4; mt++) {
        const int r0 = bm + wm + mt * 16 + gid;
        const int r1 = r0 + 8;
        #pragma unroll
        for (int nt = 0; nt < 4; nt++) {
            const int c = bn + wn + nt * 8 + tig * 2;
            const float b0 = bias[c], b1 = bias[c + 1];
            float v0 = acc[mt][nt][0] + b0;
            float v1 = acc[mt][nt][1] + b1;
            float v2 = acc[mt][nt][2] + b0;
            float v3 = acc[mt][nt][3] + b1;
            if (relu) {
                v0 = fmaxf(v0, 0.f); v1 = fmaxf(v1, 0.f);
                v2 = fmaxf(v2, 0.f); v3 = fmaxf(v3, 0.f);
            }
            if (r0 < M) *(__half2*)(Cout + (size_t)r0 * N + c) = __floats2half2_rn(v0, v1);
            if (r1 < M) *(__half2*)(Cout + (size_t)r1 * N + c) = __floats2half2_rn(v2, v3);
        }
    }
}

// ---------------- FP16 GEMM + residual + LayerNorm fused (Wo / FFN2) ----------------
// 64x256 CTA tile covers a full output row (N == 256). 8 warps (2 m x 4 n),
// warp tile 32x64, 2-stage cp.async. Epilogue: acc+bias -> smem, then warp-per-row
// residual-add + LayerNorm (same op order as the old add_ln kernel) writing
// fp32 residual stream (+ optional fp16 GEMM view).
#define LTBM 64
#define LTBN 256
#define LBPADH 264                       // B row stride in halves
#define LAS_STAGE (LTBM * APADH)         // 4608 halves
#define LBS_STAGE (TBK * LBPADH)         // 16896 halves
#define CSM_STRIDE 260
#define GEMMLN_SMEM_BYTES (2 * (LAS_STAGE + LBS_STAGE) * 2)   // 86016 (>= 64*260*4 = 66560)

__global__ __launch_bounds__(256, 2) void gemm_f16_ln(
    const __half* __restrict__ A, const __half* __restrict__ W,
    const float* __restrict__ bias, const float* __restrict__ resid,
    const float* __restrict__ gamma, const float* __restrict__ beta,
    float* __restrict__ out_f, __half* __restrict__ out_h,
    int M, int K)
{
    extern __shared__ __half sm[];
    __half* Asm = sm;                        // 2 * LAS_STAGE
    __half* Bsm = sm + 2 * LAS_STAGE;        // 2 * LBS_STAGE
    float*  Csm = (float*)sm;                // reused after mainloop

    const int tid = threadIdx.x;
    const int bm  = blockIdx.x * LTBM;

    // A tile: 64 rows x 64 halves (128B/row): threads 0..127, 2/row.
    const int row_a = tid >> 1;              // valid when tid < 128
    const int col_a = (tid & 1) << 5;
    const bool do_a = tid < 128;
    const bool a_ok = do_a && (bm + row_a) < M;
    // B tile: 64 rows x 256 halves (512B/row): 4 threads/row, 8 x 16B each.
    const int row_b = tid >> 2;
    const int col_b = (tid & 3) << 6;        // 0,64,128,192 halves

    const int w    = tid >> 5;
    const int wm   = (w & 1) * 32;
    const int wn   = (w >> 1) * 64;
    const int lane = tid & 31;
    const int gid  = lane >> 2;
    const int tig  = lane & 3;
    const int l16  = lane & 15;
    const int lhi  = (lane >> 4) << 3;

    float acc[2][8][4] = {};

    const int KT = K >> 6;

    const __half* Abase = A + (size_t)(bm + row_a) * K + col_a;
    const __half* Bbase = W + (size_t)row_b * E_ + col_b;

    __half* asm_dst[2];
    __half* bsm_dst[2];
    #pragma unroll
    for (int s = 0; s < 2; s++) {
        asm_dst[s] = Asm + s * LAS_STAGE + row_a * APADH + col_a;
        bsm_dst[s] = Bsm + s * LBS_STAGE + row_b * LBPADH + col_b;
    }

    // prologue: stage 0
    {
        if (do_a) {
            #pragma unroll
            for (int i = 0; i < 4; i++)
                cp_async16(asm_dst[0] + i * 8, Abase + i * 8, a_ok);
        }
        #pragma unroll
        for (int i = 0; i < 8; i++)
            cp_async16(bsm_dst[0] + i * 8, Bbase + i * 8, true);
        CP_COMMIT();
    }

    for (int kt = 0; kt < KT; kt++) {
        // issue next tile, then wait for current (pending <= {cur,next})
        if (kt + 1 < KT) {
            const int s  = (kt + 1) & 1;
            const int k0 = (kt + 1) << 6;
            if (do_a) {
                #pragma unroll
                for (int i = 0; i < 4; i++)
                    cp_async16(asm_dst[s] + i * 8, Abase + k0 + i * 8, a_ok);
            }
            #pragma unroll
            for (int i = 0; i < 8; i++)
                cp_async16(bsm_dst[s] + i * 8, Bbase + (size_t)k0 * E_ + i * 8, true);
        }
        CP_COMMIT();
        CP_WAIT1();
        __syncthreads();

        const __half* Ab = Asm + (kt & 1) * LAS_STAGE;
        const __half* Bb = Bsm + (kt & 1) * LBS_STAGE;

        #pragma unroll
        for (int ks = 0; ks < 4; ks++) {
            const int kk = ks << 4;
            uint32_t af[2][4];
            uint32_t bf[8][2];
            #pragma unroll
            for (int mt = 0; mt < 2; mt++) {
                const int r0 = wm + mt * 16;
                ldsm_x4(af[mt][0], af[mt][1], af[mt][2], af[mt][3],
                        Ab + (size_t)(r0 + l16) * APADH + kk + lhi);
            }
            #pragma unroll
            for (int pr = 0; pr < 4; pr++) {
                const int c0 = wn + pr * 16;
                ldsm_x4_trans(bf[pr * 2][0], bf[pr * 2][1], bf[pr * 2 + 1][0], bf[pr * 2 + 1][1],
                              Bb + (size_t)(kk + l16) * LBPADH + c0 + lhi);
            }
            #pragma unroll
            for (int mt = 0; mt < 2; mt++)
                #pragma unroll
                for (int nt = 0; nt < 8; nt++)
                    mma_f16(acc[mt][nt][0], acc[mt][nt][1], acc[mt][nt][2], acc[mt][nt][3],
                            af[mt][0], af[mt][1], af[mt][2], af[mt][3],
                            bf[nt][0], bf[nt][1]);
        }
        __syncthreads();   // smem reads done before next iteration overwrites
    }

    // stage acc+bias into smem (full 64 x 256 tile)
    #pragma unroll
    for (int mt = 0; mt < 2; mt++) {
        const int lr0 = wm + mt * 16 + gid;
        const int lr1 = lr0 + 8;
        #pragma unroll
        for (int nt = 0; nt < 8; nt++) {
            const int c = wn + nt * 8 + tig * 2;
            const float b0 = bias[c], b1 = bias[c + 1];
            Csm[lr0 * CSM_STRIDE + c]     = acc[mt][nt][0] + b0;
            Csm[lr0 * CSM_STRIDE + c + 1] = acc[mt][nt][1] + b1;
            Csm[lr1 * CSM_STRIDE + c]     = acc[mt][nt][2] + b0;
            Csm[lr1 * CSM_STRIDE + c + 1] = acc[mt][nt][3] + b1;
        }
    }
    __syncthreads();

    // residual + LayerNorm: warp w handles local rows w*8 .. w*8+7
    #pragma unroll
    for (int rr = 0; rr < 8; rr++) {
        const int lrow = w * 8 + rr;
        const int grow = bm + lrow;
        if (grow >= M) continue;

        const float* rp = resid + (size_t)grow * E_;
        const float* cp = Csm + lrow * CSM_STRIDE;

        float vals[8];
        float s = 0.f;
        #pragma unroll
        for (int i = 0; i < 8; i++) {
            vals[i] = rp[lane + i * 32] + cp[lane + i * 32];
            s += vals[i];
        }
        #pragma unroll
        for (int o = 16; o > 0; o >>= 1) s += __shfl_xor_sync(0xFFFFFFFFu, s, o);
        float mean = s * (1.f / E_);

        float vs = 0.f;
        #pragma unroll
        for (int i = 0; i < 8; i++) {
            float d = vals[i] - mean;
            vs += d * d;
        }
        #pragma unroll
        for (int o = 16; o > 0; o >>= 1) vs += __shfl_xor_sync(0xFFFFFFFFu, vs, o);
        float inv = rsqrtf(vs * (1.f / E_) + EPS);

        float* opf = out_f + (size_t)grow * E_;
        #pragma unroll
        for (int i = 0; i < 8; i++) {
            int c = lane + i * 32;
            float v = (vals[i] - mean) * inv * gamma[c] + beta[c];
            opf[c] = v;
            if (out_h) out_h[(size_t)grow * E_ + c] = __float2half(v);
        }
    }
}

// ---------------- multi-scale deformable attention (round-9 shuffle version) ----------------
__global__ __launch_bounds__(256) void deform_attn_kernel(
    const __half* __restrict__ voa, const float* __restrict__ ref,
    __half* __restrict__ out)
{
    const int gw = blockIdx.x * 8 + (threadIdx.x >> 5);
    if (gw >= MROWS * 4) return;
    const int lane = threadIdx.x & 31;
    const int hp = gw & 3;
    const int bn = gw >> 2;
    const int b  = bn / NQ;
    const int h  = hp * 2 + (lane >> 4);
    const int p  = lane & 15;
    const int lvl = p >> 2;

    const __half* offp = voa + (size_t)bn * CATN + 256 + h * 32;
    float ox = __half2float(offp[p * 2 + 0]);
    float oy = __half2float(offp[p * 2 + 1]);
    float logit = __half2float(voa[(size_t)bn * CATN + 512 + h * 16 + p]);

    float mx = logit;
    #pragma unroll
    for (int o = 8; o > 0; o >>= 1) mx = fmaxf(mx, __shfl_xor_sync(0xFFFFFFFFu, mx, o));
    float e = __expf(logit - mx);
    float ss = e;
    #pragma unroll
    for (int o = 8; o > 0; o >>= 1) ss += __shfl_xor_sync(0xFFFFFFFFu, ss, o);
    const float prob = e / ss;

    const int W = c_w[lvl], H = c_h[lvl], S = c_start[lvl];
    const float fw = (float)W, fh = (float)H;
    const float rx = ref[((size_t)bn * NLVL + lvl) * 2 + 0];
    const float ry = ref[((size_t)bn * NLVL + lvl) * 2 + 1];

    const float locx = rx + ox / fw;
    const float locy = ry + oy / fh;
    const float xs = locx * fw - 0.5f;
    const float ys = locy * fh - 0.5f;
    const float fxs = floorf(xs), fys = floorf(ys);
    const int x0 = (int)fxs, y0 = (int)fys;
    const float lx = xs - fxs, ly = ys - fys;
    const int x1 = x0 + 1, y1 = y0 + 1;

    const float vx0 = (x0 >= 0 && x0 < W) ? 1.f : 0.f;
    const float vx1 = (x1 >= 0 && x1 < W) ? 1.f : 0.f;
    const float vy0 = (y0 >= 0 && y0 < H) ? 1.f : 0.f;
    const float vy1 = (y1 >= 0 && y1 < H) ? 1.f : 0.f;

    float w00 = (1.f - lx) * (1.f - ly) * prob * vy0 * vx0;
    float w01 = lx * (1.f - ly) * prob * vy0 * vx1;
    float w10 = (1.f - lx) * ly * prob * vy1 * vx0;
    float w11 = lx * ly * prob * vy1 * vx1;

    const int x0c = min(max(x0, 0), W - 1);
    const int x1c = min(max(x1, 0), W - 1);
    const int y0c = min(max(y0, 0), H - 1);
    const int y1c = min(max(y1, 0), H - 1);

    int r00 = S + y0c * W + x0c;
    int r01 = S + y0c * W + x1c;
    int r10 = S + y1c * W + x0c;
    int r11 = S + y1c * W + x1c;

    const int l16 = lane & 15;
    const __half2* vbase = (const __half2*)(voa + (size_t)b * NQ * CATN + h * HDIM) + l16;
    const int ROWH2 = CATN / 2;

    float2 acc = make_float2(0.f, 0.f);

    #pragma unroll
    for (int q = 0; q < 16; q++) {
        const int   i00 = __shfl_sync(0xFFFFFFFFu, r00, q, 16);
        const int   i01 = __shfl_sync(0xFFFFFFFFu, r01, q, 16);
        const int   i10 = __shfl_sync(0xFFFFFFFFu, r10, q, 16);
        const int   i11 = __shfl_sync(0xFFFFFFFFu, r11, q, 16);
        const float a00 = __shfl_sync(0xFFFFFFFFu, w00, q, 16);
        const float a01 = __shfl_sync(0xFFFFFFFFu, w01, q, 16);
        const float a10 = __shfl_sync(0xFFFFFFFFu, w10, q, 16);
        const float a11 = __shfl_sync(0xFFFFFFFFu, w11, q, 16);

        const float2 f00 = __half22float2(vbase[(size_t)i00 * ROWH2]);
        const float2 f01 = __half22float2(vbase[(size_t)i01 * ROWH2]);
        const float2 f10 = __half22float2(vbase[(size_t)i10 * ROWH2]);
        const float2 f11 = __half22float2(vbase[(size_t)i11 * ROWH2]);

        acc.x += a00 * f00.x + a01 * f01.x + a10 * f10.x + a11 * f11.x;
        acc.y += a00 * f00.y + a01 * f01.y + a10 * f10.y + a11 * f11.y;
    }

    __half2* op = (__half2*)(out + (size_t)bn * E_ + h * HDIM) + l16;
    *op = __floats2half2_rn(acc.x, acc.y);
}

// ---------------- launchers ----------------
static inline void run_gemm(const __half* A, const __half* W, const float* b,
                            __half* C, int M, int K, int Nc, int relu) {
    dim3 grid(Nc / TBN, (M + TBM - 1) / TBM);
    gemm_f16<<<grid, 256, GEMM_SMEM_BYTES>>>(A, W, b, C, M, K, Nc, relu);
}

static inline void run_gemm_ln(const __half* A, const __half* W, const float* b,
                               const float* resid, const float* gamma, const float* beta,
                               float* out_f, __half* out_h, int M, int K) {
    int grid = (M + LTBM - 1) / LTBM;
    gemm_f16_ln<<<grid, 256, GEMMLN_SMEM_BYTES>>>(A, W, b, resid, gamma, beta, out_f, out_h, M, K);
}

extern "C" void kernel_launch(void* const* d_in, const int* in_sizes, int n_in,
                              void* d_out, int out_size) {
    const float* src  = (const float*)d_in[0];
    const float* ref  = (const float*)d_in[1];
    const float* Woff = (const float*)d_in[4];
    const float* boff = (const float*)d_in[5];
    const float* Waw  = (const float*)d_in[6];
    const float* baw  = (const float*)d_in[7];
    const float* Wv   = (const float*)d_in[8];
    const float* bv   = (const float*)d_in[9];
    const float* Wo   = (const float*)d_in[10];
    const float* bo   = (const float*)d_in[11];
    const float* ln1g = (const float*)d_in[12];
    const float* ln1b = (const float*)d_in[13];
    const float* Wf1  = (const float*)d_in[14];
    const float* bf1  = (const float*)d_in[15];
    const float* Wf2  = (const float*)d_in[16];
    const float* bf2  = (const float*)d_in[17];
    const float* ln2g = (const float*)d_in[18];
    const float* ln2b = (const float*)d_in[19];
    float* out = (float*)d_out;

    cudaFuncSetAttribute(gemm_f16,    cudaFuncAttributeMaxDynamicSharedMemorySize, GEMM_SMEM_BYTES);
    cudaFuncSetAttribute(gemm_f16_ln, cudaFuncAttributeMaxDynamicSharedMemorySize, GEMMLN_SMEM_BYTES);

    float *px, *pbcat;
    __half *pxh, *pvoa, *psamp, *pffn, *pwcat, *pwo, *pwf1, *pwf2;
    cudaGetSymbolAddress((void**)&px,    g_x);
    cudaGetSymbolAddress((void**)&pxh,   g_xh);
    cudaGetSymbolAddress((void**)&pvoa,  g_voa);
    cudaGetSymbolAddress((void**)&psamp, g_samp);
    cudaGetSymbolAddress((void**)&pffn,  g_ffn);
    cudaGetSymbolAddress((void**)&pwcat, g_wcat);
    cudaGetSymbolAddress((void**)&pbcat, g_bcat);
    cudaGetSymbolAddress((void**)&pwo,   g_wo);
    cudaGetSymbolAddress((void**)&pwf1,  g_wf1);
    cudaGetSymbolAddress((void**)&pwf2,  g_wf2);

    const int M = MROWS;
    const int nElem = M * E_;

    src_copy_kernel<<<(nElem + 255) / 256, 256>>>(src, px, pxh, nElem);
    prep_weights_kernel<<<(PREP_TOTAL + 255) / 256, 256>>>(
        Wv, Woff, Waw, bv, boff, baw, Wo, Wf1, Wf2,
        pwcat, pbcat, pwo, pwf1, pwf2);

    const int dwarps = M * 4;
    const int dgrid  = (dwarps + 7) / 8;

    for (int layer = 0; layer < 6; layer++) {
        // fused projections: [v | off | aw-logits], fp16 out
        run_gemm(pxh, pwcat, pbcat, pvoa, M, E_, CATN, 0);

        deform_attn_kernel<<<dgrid, 256>>>(pvoa, ref, psamp);

        // Wo GEMM + residual + LN1 fused (x <- LN(x + samp@Wo))
        run_gemm_ln(psamp, pwo, bo, px, ln1g, ln1b, px, pxh, M, E_);

        // FFN1 (relu, fp16 out)
        run_gemm(pxh, pwf1, bf1, pffn, M, E_, F_, 1);

        // FFN2 GEMM + residual + LN2 fused
        float*  dst  = (layer == 5) ? out : px;
        __half* dsth = (layer == 5) ? (__half*)nullptr : pxh;
        run_gemm_ln(pffn, pwf2, bf2, px, ln2g, ln2b, dst, dsth, M, F_);
    }
}

// round 12
// speedup vs baseline: 1.0664x; 1.0664x over previous
#include <cuda_runtime.h>
#include <cuda_fp16.h>
#include <math.h>
#include <stdint.h>

// ---------------- static problem config ----------------
#define NQ     13294
#define BATCH  2
#define MROWS  (BATCH * NQ)     // 26588
#define E_     256
#define F_     1024
#define CATN   640              // concat proj width: 256 (v) + 256 (off) + 128 (aw)
#define NHEAD  8
#define HDIM   32
#define NLVL   4
#define NPNT   4
#define EPS    1e-5f

// ---------------- scratch (static device globals; no allocation) ----------------
__device__ float  g_x   [MROWS * E_];    // fp32 residual stream
__device__ __half g_xh  [MROWS * E_];    // fp16 view for GEMM A
__device__ __half g_voa [MROWS * CATN];  // [v | off | aw-logits] fp16
__device__ __half g_samp[MROWS * E_];    // deform output (GEMM A)
__device__ float  g_tmp [MROWS * E_];    // fp32 branch output (pre-LN)
__device__ __half g_ffn [MROWS * F_];    // FFN hidden
__device__ __half g_wcat[E_ * CATN];
__device__ float  g_bcat[CATN];
__device__ __half g_wo  [E_ * E_];
__device__ __half g_wf1 [E_ * F_];
__device__ __half g_wf2 [F_ * E_];

__constant__ int c_w[NLVL]     = {100, 50, 25, 13};
__constant__ int c_h[NLVL]     = {100, 50, 25, 13};
__constant__ int c_start[NLVL] = {0, 10000, 12500, 13125};

// ---------------- prep kernels (2 launches total) ----------------
__global__ void src_copy_kernel(const float* __restrict__ src,
                                float* __restrict__ xf, __half* __restrict__ xh, int n) {
    int i = blockIdx.x * blockDim.x + threadIdx.x;
    if (i < n) { float v = src[i]; xf[i] = v; xh[i] = __float2half(v); }
}

#define WCAT_N (E_ * CATN)
#define WO_N   (E_ * E_)
#define WF1_N  (E_ * F_)
#define WF2_N  (F_ * E_)
#define PREP_TOTAL (WCAT_N + WO_N + WF1_N + WF2_N)

__global__ void prep_weights_kernel(
    const float* __restrict__ Wv, const float* __restrict__ Woff, const float* __restrict__ Waw,
    const float* __restrict__ bv, const float* __restrict__ boff, const float* __restrict__ baw,
    const float* __restrict__ Wo, const float* __restrict__ Wf1, const float* __restrict__ Wf2,
    __half* __restrict__ wcat, float* __restrict__ bcat,
    __half* __restrict__ wo, __half* __restrict__ wf1, __half* __restrict__ wf2)
{
    int i = blockIdx.x * blockDim.x + threadIdx.x;
    if (i < WCAT_N) {
        int r = i / CATN, c = i % CATN;
        float v;
        if (c < 256)      v = Wv  [r * 256 + c];
        else if (c < 512) v = Woff[r * 256 + (c - 256)];
        else              v = Waw [r * 128 + (c - 512)];
        wcat[i] = __float2half(v);
    } else if (i < WCAT_N + WO_N) {
        int j = i - WCAT_N;
        wo[j] = __float2half(Wo[j]);
    } else if (i < WCAT_N + WO_N + WF1_N) {
        int j = i - WCAT_N - WO_N;
        wf1[j] = __float2half(Wf1[j]);
    } else if (i < PREP_TOTAL) {
        int j = i - WCAT_N - WO_N - WF1_N;
        wf2[j] = __float2half(Wf2[j]);
    }
    if (i < CATN) {
        bcat[i] = (i < 256) ? bv[i] : (i < 512) ? boff[i - 256] : baw[i - 512];
    }
}

// ---------------- cp.async helpers ----------------
__device__ __forceinline__ void cp_async16(void* smem_dst, const void* gmem_src, bool pred) {
    uint32_t saddr = (uint32_t)__cvta_generic_to_shared(smem_dst);
    int sz = pred ? 16 : 0;
    asm volatile("cp.async.cg.shared.global [%0], [%1], 16, %2;\n"
                 :: "r"(saddr), "l"(gmem_src), "r"(sz));
}
#define CP_COMMIT() asm volatile("cp.async.commit_group;\n" ::: "memory")
#define CP_WAIT1()  asm volatile("cp.async.wait_group 1;\n" ::: "memory")

// ---------------- FP16 tensor-core GEMM ----------------
#define TBM 128
#define TBN 128
#define TBK 64
#define APADH 72
#define BPADH 136
#define NSTAGE 3
#define AS_STAGE (TBM * APADH)
#define BS_STAGE (TBK * BPADH)
#define GEMM_SMEM_BYTES ((NSTAGE * (AS_STAGE + BS_STAGE)) * 2)   // 107520

__device__ __forceinline__ void mma_f16(
    float& d0, float& d1, float& d2, float& d3,
    uint32_t a0, uint32_t a1, uint32_t a2, uint32_t a3,
    uint32_t b0, uint32_t b1)
{
    asm volatile(
        "mma.sync.aligned.m16n8k16.row.col.f32.f16.f16.f32 "
        "{%0,%1,%2,%3}, {%4,%5,%6,%7}, {%8,%9}, {%0,%1,%2,%3};"
        : "+f"(d0), "+f"(d1), "+f"(d2), "+f"(d3)
        : "r"(a0), "r"(a1), "r"(a2), "r"(a3), "r"(b0), "r"(b1));
}

__device__ __forceinline__ void ldsm_x4(uint32_t& r0, uint32_t& r1, uint32_t& r2, uint32_t& r3,
                                        const __half* p) {
    uint32_t addr = (uint32_t)__cvta_generic_to_shared(p);
    asm volatile("ldmatrix.sync.aligned.m8n8.x4.shared.b16 {%0,%1,%2,%3}, [%4];"
                 : "=r"(r0), "=r"(r1), "=r"(r2), "=r"(r3) : "r"(addr));
}

__device__ __forceinline__ void ldsm_x4_trans(uint32_t& r0, uint32_t& r1, uint32_t& r2, uint32_t& r3,
                                              const __half* p) {
    uint32_t addr = (uint32_t)__cvta_generic_to_shared(p);
    asm volatile("ldmatrix.sync.aligned.m8n8.x4.trans.shared.b16 {%0,%1,%2,%3}, [%4];"
                 : "=r"(r0), "=r"(r1), "=r"(r2), "=r"(r3) : "r"(addr));
}

__global__ __launch_bounds__(256, 2) void gemm_f16(
    const __half* __restrict__ A, const __half* __restrict__ W,
    const float* __restrict__ bias, void* __restrict__ Cout,
    int M, int K, int N, int relu, int out_half)
{
    extern __shared__ __half sm[];
    __half* Asm = sm;
    __half* Bsm = sm + NSTAGE * AS_STAGE;

    const int tid = threadIdx.x;
    const int bm  = blockIdx.y * TBM;
    const int bn  = blockIdx.x * TBN;

    const int row_a = tid >> 1;
    const int col_a = (tid & 1) << 5;
    const int row_b = tid >> 2;
    const int col_b = (tid & 3) << 5;

    const bool a_ok = (bm + row_a) < M;

    const int w    = tid >> 5;
    const int wm   = (w & 1) * 64;
    const int wn   = (w >> 1) * 32;
    const int lane = tid & 31;
    const int gid  = lane >> 2;
    const int tig  = lane & 3;
    const int l16  = lane & 15;
    const int lhi  = (lane >> 4) << 3;

    float acc[4][4][4] = {};

    const int KT = K >> 6;

    const __half* Abase = A + (size_t)(bm + row_a) * K + col_a;
    const __half* Bbase = W + (size_t)row_b * N + bn + col_b;

    __half* asm_dst[NSTAGE];
    __half* bsm_dst[NSTAGE];
    #pragma unroll
    for (int s = 0; s < NSTAGE; s++) {
        asm_dst[s] = Asm + s * AS_STAGE + row_a * APADH + col_a;
        bsm_dst[s] = Bsm + s * BS_STAGE + row_b * BPADH + col_b;
    }

    #pragma unroll
    for (int s = 0; s < NSTAGE - 1; s++) {
        const int k0 = s << 6;
        #pragma unroll
        for (int i = 0; i < 4; i++) {
            cp_async16(asm_dst[s] + i * 8, Abase + k0 + i * 8, a_ok);
            cp_async16(bsm_dst[s] + i * 8, Bbase + (size_t)k0 * N + i * 8, true);
        }
        CP_COMMIT();
    }

    for (int kt = 0; kt < KT; kt++) {
        CP_WAIT1();
        __syncthreads();

        if (kt + NSTAGE - 1 < KT) {
            const int s  = (kt + NSTAGE - 1) % NSTAGE;
            const int k0 = (kt + NSTAGE - 1) << 6;
            #pragma unroll
            for (int i = 0; i < 4; i++) {
                cp_async16(asm_dst[s] + i * 8, Abase + k0 + i * 8, a_ok);
                cp_async16(bsm_dst[s] + i * 8, Bbase + (size_t)k0 * N + i * 8, true);
            }
        }
        CP_COMMIT();

        const __half* Ab = Asm + (kt % NSTAGE) * AS_STAGE;
        const __half* Bb = Bsm + (kt % NSTAGE) * BS_STAGE;

        #pragma unroll
        for (int ks = 0; ks < 4; ks++) {
            const int kk = ks << 4;
            uint32_t af[4][4];
            uint32_t bf[4][2];
            #pragma unroll
            for (int mt = 0; mt < 4; mt++) {
                const int r0 = wm + mt * 16;
                ldsm_x4(af[mt][0], af[mt][1], af[mt][2], af[mt][3],
                        Ab + (size_t)(r0 + l16) * APADH + kk + lhi);
            }
            #pragma unroll
            for (int pr = 0; pr < 2; pr++) {
                const int c0 = wn + pr * 16;
                ldsm_x4_trans(bf[pr * 2][0], bf[pr * 2][1], bf[pr * 2 + 1][0], bf[pr * 2 + 1][1],
                              Bb + (size_t)(kk + l16) * BPADH + c0 + lhi);
            }
            #pragma unroll
            for (int mt = 0; mt < 4; mt++)
                #pragma unroll
                for (int nt = 0; nt < 4; nt++)
                    mma_f16(acc[mt][nt][0], acc[mt][nt][1], acc[mt][nt][2], acc[mt][nt][3],
                            af[mt][0], af[mt][1], af[mt][2], af[mt][3],
                            bf[nt][0], bf[nt][1]);
        }
    }

    float*  Cf = (float*)Cout;
    __half* Ch = (__half*)Cout;
    #pragma unroll
    for (int mt = 0; mt < 4; mt++) {
        const int r0 = bm + wm + mt * 16 + gid;
        const int r1 = r0 + 8;
        #pragma unroll
        for (int nt = 0; nt < 4; nt++) {
            const int c = bn + wn + nt * 8 + tig * 2;
            const float b0 = bias[c], b1 = bias[c + 1];
            float v0 = acc[mt][nt][0] + b0;
            float v1 = acc[mt][nt][1] + b1;
            float v2 = acc[mt][nt][2] + b0;
            float v3 = acc[mt][nt][3] + b1;
            if (relu) {
                v0 = fmaxf(v0, 0.f); v1 = fmaxf(v1, 0.f);
                v2 = fmaxf(v2, 0.f); v3 = fmaxf(v3, 0.f);
            }
            if (out_half) {
                if (r0 < M) *(__half2*)(Ch + (size_t)r0 * N + c) = __floats2half2_rn(v0, v1);
                if (r1 < M) *(__half2*)(Ch + (size_t)r1 * N + c) = __floats2half2_rn(v2, v3);
            } else {
                if (r0 < M) *(float2*)(Cf + (size_t)r0 * N + c) = make_float2(v0, v1);
                if (r1 < M) *(float2*)(Cf + (size_t)r1 * N + c) = make_float2(v2, v3);
            }
        }
    }
}

// ---------------- multi-scale deformable attention v4 ----------------
// One warp = (query, head-pair). Each lane computes ONE point's params,
// then packs them: 4 corner indices -> 2 uints (16-bit each), 4 bilinear
// weights -> 2 half2. Gather loop broadcasts with 4 shuffles per point
// (was 8), plus 4 coalesced half2 gathers. MIO ops/point: 12 -> 8.
__global__ __launch_bounds__(256) void deform_attn_kernel(
    const __half* __restrict__ voa, const float* __restrict__ ref,
    __half* __restrict__ out)
{
    const int gw = blockIdx.x * 8 + (threadIdx.x >> 5);
    if (gw >= MROWS * 4) return;
    const int lane = threadIdx.x & 31;
    const int hp = gw & 3;
    const int bn = gw >> 2;
    const int b  = bn / NQ;
    const int h  = hp * 2 + (lane >> 4);
    const int p  = lane & 15;
    const int lvl = p >> 2;

    // ---- phase 1: per-lane point math ----
    const __half* offp = voa + (size_t)bn * CATN + 256 + h * 32;
    float ox = __half2float(offp[p * 2 + 0]);
    float oy = __half2float(offp[p * 2 + 1]);
    float logit = __half2float(voa[(size_t)bn * CATN + 512 + h * 16 + p]);

    float mx = logit;
    #pragma unroll
    for (int o = 8; o > 0; o >>= 1) mx = fmaxf(mx, __shfl_xor_sync(0xFFFFFFFFu, mx, o));
    float e = __expf(logit - mx);
    float ss = e;
    #pragma unroll
    for (int o = 8; o > 0; o >>= 1) ss += __shfl_xor_sync(0xFFFFFFFFu, ss, o);
    const float prob = e / ss;

    const int W = c_w[lvl], H = c_h[lvl], S = c_start[lvl];
    const float fw = (float)W, fh = (float)H;
    const float rx = ref[((size_t)bn * NLVL + lvl) * 2 + 0];
    const float ry = ref[((size_t)bn * NLVL + lvl) * 2 + 1];

    const float locx = rx + ox / fw;
    const float locy = ry + oy / fh;
    const float xs = locx * fw - 0.5f;
    const float ys = locy * fh - 0.5f;
    const float fxs = floorf(xs), fys = floorf(ys);
    const int x0 = (int)fxs, y0 = (int)fys;
    const float lx = xs - fxs, ly = ys - fys;
    const int x1 = x0 + 1, y1 = y0 + 1;

    const float vx0 = (x0 >= 0 && x0 < W) ? 1.f : 0.f;
    const float vx1 = (x1 >= 0 && x1 < W) ? 1.f : 0.f;
    const float vy0 = (y0 >= 0 && y0 < H) ? 1.f : 0.f;
    const float vy1 = (y1 >= 0 && y1 < H) ? 1.f : 0.f;

    const float w00 = (1.f - lx) * (1.f - ly) * prob * vy0 * vx0;
    const float w01 = lx * (1.f - ly) * prob * vy0 * vx1;
    const float w10 = (1.f - lx) * ly * prob * vy1 * vx0;
    const float w11 = lx * ly * prob * vy1 * vx1;

    const int x0c = min(max(x0, 0), W - 1);
    const int x1c = min(max(x1, 0), W - 1);
    const int y0c = min(max(y0, 0), H - 1);
    const int y1c = min(max(y1, 0), H - 1);

    // pack: indices 16-bit x2, weights half2 x2
    uint32_t ridx0 = (uint32_t)(S + y0c * W + x0c) | ((uint32_t)(S + y0c * W + x1c) << 16);
    uint32_t ridx1 = (uint32_t)(S + y1c * W + x0c) | ((uint32_t)(S + y1c * W + x1c) << 16);
    __half2 wl = __floats2half2_rn(w00, w01);
    __half2 wh = __floats2half2_rn(w10, w11);
    uint32_t wp0 = *(uint32_t*)&wl;
    uint32_t wp1 = *(uint32_t*)&wh;

    // ---- phase 2: gather 32 channels per head (16 lanes x half2) ----
    const int l16 = lane & 15;
    const __half2* vbase = (const __half2*)(voa + (size_t)b * NQ * CATN + h * HDIM) + l16;
    const int ROWH2 = CATN / 2;

    float2 acc = make_float2(0.f, 0.f);

    #pragma unroll
    for (int q = 0; q < 16; q++) {
        const uint32_t i01p = __shfl_sync(0xFFFFFFFFu, ridx0, q, 16);
        const uint32_t i23p = __shfl_sync(0xFFFFFFFFu, ridx1, q, 16);
        const uint32_t a01p = __shfl_sync(0xFFFFFFFFu, wp0, q, 16);
        const uint32_t a23p = __shfl_sync(0xFFFFFFFFu, wp1, q, 16);

        const int i00 = i01p & 0xFFFF, i01 = i01p >> 16;
        const int i10 = i23p & 0xFFFF, i11 = i23p >> 16;
        const float2 alo = __half22float2(*(const __half2*)&a01p);
        const float2 ahi = __half22float2(*(const __half2*)&a23p);

        const float2 f00 = __half22float2(vbase[(size_t)i00 * ROWH2]);
        const float2 f01 = __half22float2(vbase[(size_t)i01 * ROWH2]);
        const float2 f10 = __half22float2(vbase[(size_t)i10 * ROWH2]);
        const float2 f11 = __half22float2(vbase[(size_t)i11 * ROWH2]);

        acc.x += alo.x * f00.x + alo.y * f01.x + ahi.x * f10.x + ahi.y * f11.x;
        acc.y += alo.x * f00.y + alo.y * f01.y + ahi.x * f10.y + ahi.y * f11.y;
    }

    __half2* op = (__half2*)(out + (size_t)bn * E_ + h * HDIM) + l16;
    *op = __floats2half2_rn(acc.x, acc.y);
}

// ---------------- fused residual add + LayerNorm (warp per row) ----------------
__global__ __launch_bounds__(256) void add_ln_kernel(
    const float* __restrict__ x, const float* __restrict__ r,
    const float* __restrict__ gamma, const float* __restrict__ beta,
    float* __restrict__ out_f, __half* __restrict__ out_h, int M)
{
    int row = blockIdx.x * 8 + (threadIdx.x >> 5);
    if (row >= M) return;
    int lane = threadIdx.x & 31;

    const float* xp = x + (size_t)row * E_;
    const float* rp = r + (size_t)row * E_;

    float vals[8];
    float s = 0.f;
    #pragma unroll
    for (int i = 0; i < 8; i++) {
        vals[i] = xp[lane + i * 32] + rp[lane + i * 32];
        s += vals[i];
    }
    #pragma unroll
    for (int o = 16; o > 0; o >>= 1) s += __shfl_xor_sync(0xFFFFFFFFu, s, o);
    float mean = s * (1.f / E_);

    float vs = 0.f;
    #pragma unroll
    for (int i = 0; i < 8; i++) {
        float d = vals[i] - mean;
        vs += d * d;
    }
    #pragma unroll
    for (int o = 16; o > 0; o >>= 1) vs += __shfl_xor_sync(0xFFFFFFFFu, vs, o);
    float inv = rsqrtf(vs * (1.f / E_) + EPS);

    float* opf = out_f + (size_t)row * E_;
    #pragma unroll
    for (int i = 0; i < 8; i++) {
        int c = lane + i * 32;
        float v = (vals[i] - mean) * inv * gamma[c] + beta[c];
        opf[c] = v;
        if (out_h) out_h[(size_t)row * E_ + c] = __float2half(v);
    }
}

// ---------------- launcher ----------------
static inline void run_gemm(const __half* A, const __half* W, const float* b,
                            void* C, int M, int K, int Nc, int relu, int out_half) {
    dim3 grid(Nc / TBN, (M + TBM - 1) / TBM);
    gemm_f16<<<grid, 256, GEMM_SMEM_BYTES>>>(A, W, b, C, M, K, Nc, relu, out_half);
}

extern "C" void kernel_launch(void* const* d_in, const int* in_sizes, int n_in,
                              void* d_out, int out_size) {
    const float* src  = (const float*)d_in[0];
    const float* ref  = (const float*)d_in[1];
    const float* Woff = (const float*)d_in[4];
    const float* boff = (const float*)d_in[5];
    const float* Waw  = (const float*)d_in[6];
    const float* baw  = (const float*)d_in[7];
    const float* Wv   = (const float*)d_in[8];
    const float* bv   = (const float*)d_in[9];
    const float* Wo   = (const float*)d_in[10];
    const float* bo   = (const float*)d_in[11];
    const float* ln1g = (const float*)d_in[12];
    const float* ln1b = (const float*)d_in[13];
    const float* Wf1  = (const float*)d_in[14];
    const float* bf1  = (const float*)d_in[15];
    const float* Wf2  = (const float*)d_in[16];
    const float* bf2  = (const float*)d_in[17];
    const float* ln2g = (const float*)d_in[18];
    const float* ln2b = (const float*)d_in[19];
    float* out = (float*)d_out;

    cudaFuncSetAttribute(gemm_f16, cudaFuncAttributeMaxDynamicSharedMemorySize, GEMM_SMEM_BYTES);

    float *px, *ptmp, *pbcat;
    __half *pxh, *pvoa, *psamp, *pffn, *pwcat, *pwo, *pwf1, *pwf2;
    cudaGetSymbolAddress((void**)&px,    g_x);
    cudaGetSymbolAddress((void**)&pxh,   g_xh);
    cudaGetSymbolAddress((void**)&pvoa,  g_voa);
    cudaGetSymbolAddress((void**)&psamp, g_samp);
    cudaGetSymbolAddress((void**)&ptmp,  g_tmp);
    cudaGetSymbolAddress((void**)&pffn,  g_ffn);
    cudaGetSymbolAddress((void**)&pwcat, g_wcat);
    cudaGetSymbolAddress((void**)&pbcat, g_bcat);
    cudaGetSymbolAddress((void**)&pwo,   g_wo);
    cudaGetSymbolAddress((void**)&pwf1,  g_wf1);
    cudaGetSymbolAddress((void**)&pwf2,  g_wf2);

    const int M = MROWS;
    const int nElem = M * E_;

    src_copy_kernel<<<(nElem + 255) / 256, 256>>>(src, px, pxh, nElem);
    prep_weights_kernel<<<(PREP_TOTAL + 255) / 256, 256>>>(
        Wv, Woff, Waw, bv, boff, baw, Wo, Wf1, Wf2,
        pwcat, pbcat, pwo, pwf1, pwf2);

    const int dwarps = M * 4;
    const int dgrid  = (dwarps + 7) / 8;

    for (int layer = 0; layer < 6; layer++) {
        // fused projections: [v | off | aw-logits], fp16 out
        run_gemm(pxh, pwcat, pbcat, pvoa, M, E_, CATN, 0, 1);

        deform_attn_kernel<<<dgrid, 256>>>(pvoa, ref, psamp);

        run_gemm(psamp, pwo, bo, ptmp, M, E_, E_, 0, 0);                 // fp32 out
        add_ln_kernel<<<(M + 7) / 8, 256>>>(px, ptmp, ln1g, ln1b, px, pxh, M);

        run_gemm(pxh,  pwf1, bf1, pffn, M, E_, F_, 1, 1);                // relu, fp16 out
        run_gemm(pffn, pwf2, bf2, ptmp, M, F_, E_, 0, 0);                // fp32 out

        float* dst = (layer == 5) ? out : px;
        __half* dsth = (layer == 5) ? (__half*)nullptr : pxh;
        add_ln_kernel<<<(M + 7) / 8, 256>>>(px, ptmp, ln2g, ln2b, dst, dsth, M);
    }
}

// round 13
// speedup vs baseline: 1.1047x; 1.0359x over previous
#include <cuda_runtime.h>
#include <cuda_fp16.h>
#include <math.h>
#include <stdint.h>

// ---------------- static problem config ----------------
#define NQ     13294
#define BATCH  2
#define MROWS  (BATCH * NQ)     // 26588
#define E_     256
#define F_     1024
#define CATN   640              // concat proj width: 256 (v) + 256 (off) + 128 (aw)
#define NHEAD  8
#define HDIM   32
#define NLVL   4
#define NPNT   4
#define EPS    1e-5f

// ---------------- scratch (static device globals; no allocation) ----------------
__device__ float  g_x   [MROWS * E_];    // fp32 residual stream
__device__ __half g_xh  [MROWS * E_];    // fp16 view for GEMM A
__device__ __half g_voa [MROWS * CATN];  // [v | off | aw-logits] fp16
__device__ __half g_samp[MROWS * E_];    // deform output (GEMM A)
__device__ __half g_tmph[MROWS * E_];    // fp16 branch output (pre-LN)
__device__ __half g_ffn [MROWS * F_];    // FFN hidden
__device__ __half g_wcat[E_ * CATN];
__device__ float  g_bcat[CATN];
__device__ __half g_wo  [E_ * E_];
__device__ __half g_wf1 [E_ * F_];
__device__ __half g_wf2 [F_ * E_];

__constant__ int c_w[NLVL]     = {100, 50, 25, 13};
__constant__ int c_h[NLVL]     = {100, 50, 25, 13};
__constant__ int c_start[NLVL] = {0, 10000, 12500, 13125};

// ---------------- prep kernels (2 launches total) ----------------
__global__ void src_copy_kernel(const float* __restrict__ src,
                                float* __restrict__ xf, __half* __restrict__ xh, int n) {
    int i = blockIdx.x * blockDim.x + threadIdx.x;
    if (i < n) { float v = src[i]; xf[i] = v; xh[i] = __float2half(v); }
}

#define WCAT_N (E_ * CATN)
#define WO_N   (E_ * E_)
#define WF1_N  (E_ * F_)
#define WF2_N  (F_ * E_)
#define PREP_TOTAL (WCAT_N + WO_N + WF1_N + WF2_N)

__global__ void prep_weights_kernel(
    const float* __restrict__ Wv, const float* __restrict__ Woff, const float* __restrict__ Waw,
    const float* __restrict__ bv, const float* __restrict__ boff, const float* __restrict__ baw,
    const float* __restrict__ Wo, const float* __restrict__ Wf1, const float* __restrict__ Wf2,
    __half* __restrict__ wcat, float* __restrict__ bcat,
    __half* __restrict__ wo, __half* __restrict__ wf1, __half* __restrict__ wf2)
{
    int i = blockIdx.x * blockDim.x + threadIdx.x;
    if (i < WCAT_N) {
        int r = i / CATN, c = i % CATN;
        float v;
        if (c < 256)      v = Wv  [r * 256 + c];
        else if (c < 512) v = Woff[r * 256 + (c - 256)];
        else              v = Waw [r * 128 + (c - 512)];
        wcat[i] = __float2half(v);
    } else if (i < WCAT_N + WO_N) {
        int j = i - WCAT_N;
        wo[j] = __float2half(Wo[j]);
    } else if (i < WCAT_N + WO_N + WF1_N) {
        int j = i - WCAT_N - WO_N;
        wf1[j] = __float2half(Wf1[j]);
    } else if (i < PREP_TOTAL) {
        int j = i - WCAT_N - WO_N - WF1_N;
        wf2[j] = __float2half(Wf2[j]);
    }
    if (i < CATN) {
        bcat[i] = (i < 256) ? bv[i] : (i < 512) ? boff[i - 256] : baw[i - 512];
    }
}

// ---------------- cp.async helpers ----------------
__device__ __forceinline__ void cp_async16(void* smem_dst, const void* gmem_src, bool pred) {
    uint32_t saddr = (uint32_t)__cvta_generic_to_shared(smem_dst);
    int sz = pred ? 16 : 0;
    asm volatile("cp.async.cg.shared.global [%0], [%1], 16, %2;\n"
                 :: "r"(saddr), "l"(gmem_src), "r"(sz));
}
#define CP_COMMIT() asm volatile("cp.async.commit_group;\n" ::: "memory")
#define CP_WAIT1()  asm volatile("cp.async.wait_group 1;\n" ::: "memory")

// ---------------- FP16 tensor-core GEMM ----------------
#define TBM 128
#define TBN 128
#define TBK 64
#define APADH 72
#define BPADH 136
#define NSTAGE 3
#define AS_STAGE (TBM * APADH)
#define BS_STAGE (TBK * BPADH)
#define GEMM_SMEM_BYTES ((NSTAGE * (AS_STAGE + BS_STAGE)) * 2)   // 107520

__device__ __forceinline__ void mma_f16(
    float& d0, float& d1, float& d2, float& d3,
    uint32_t a0, uint32_t a1, uint32_t a2, uint32_t a3,
    uint32_t b0, uint32_t b1)
{
    asm volatile(
        "mma.sync.aligned.m16n8k16.row.col.f32.f16.f16.f32 "
        "{%0,%1,%2,%3}, {%4,%5,%6,%7}, {%8,%9}, {%0,%1,%2,%3};"
        : "+f"(d0), "+f"(d1), "+f"(d2), "+f"(d3)
        : "r"(a0), "r"(a1), "r"(a2), "r"(a3), "r"(b0), "r"(b1));
}

__device__ __forceinline__ void ldsm_x4(uint32_t& r0, uint32_t& r1, uint32_t& r2, uint32_t& r3,
                                        const __half* p) {
    uint32_t addr = (uint32_t)__cvta_generic_to_shared(p);
    asm volatile("ldmatrix.sync.aligned.m8n8.x4.shared.b16 {%0,%1,%2,%3}, [%4];"
                 : "=r"(r0), "=r"(r1), "=r"(r2), "=r"(r3) : "r"(addr));
}

__device__ __forceinline__ void ldsm_x4_trans(uint32_t& r0, uint32_t& r1, uint32_t& r2, uint32_t& r3,
                                              const __half* p) {
    uint32_t addr = (uint32_t)__cvta_generic_to_shared(p);
    asm volatile("ldmatrix.sync.aligned.m8n8.x4.trans.shared.b16 {%0,%1,%2,%3}, [%4];"
                 : "=r"(r0), "=r"(r1), "=r"(r2), "=r"(r3) : "r"(addr));
}

__global__ __launch_bounds__(256, 2) void gemm_f16(
    const __half* __restrict__ A, const __half* __restrict__ W,
    const float* __restrict__ bias, __half* __restrict__ Cout,
    int M, int K, int N, int relu)
{
    extern __shared__ __half sm[];
    __half* Asm = sm;
    __half* Bsm = sm + NSTAGE * AS_STAGE;

    const int tid = threadIdx.x;
    const int bm  = blockIdx.y * TBM;
    const int bn  = blockIdx.x * TBN;

    const int row_a = tid >> 1;
    const int col_a = (tid & 1) << 5;
    const int row_b = tid >> 2;
    const int col_b = (tid & 3) << 5;

    const bool a_ok = (bm + row_a) < M;

    const int w    = tid >> 5;
    const int wm   = (w & 1) * 64;
    const int wn   = (w >> 1) * 32;
    const int lane = tid & 31;
    const int gid  = lane >> 2;
    const int tig  = lane & 3;
    const int l16  = lane & 15;
    const int lhi  = (lane >> 4) << 3;

    float acc[4][4][4] = {};

    const int KT = K >> 6;

    const __half* Abase = A + (size_t)(bm + row_a) * K + col_a;
    const __half* Bbase = W + (size_t)row_b * N + bn + col_b;

    __half* asm_dst[NSTAGE];
    __half* bsm_dst[NSTAGE];
    #pragma unroll
    for (int s = 0; s < NSTAGE; s++) {
        asm_dst[s] = Asm + s * AS_STAGE + row_a * APADH + col_a;
        bsm_dst[s] = Bsm + s * BS_STAGE + row_b * BPADH + col_b;
    }

    #pragma unroll
    for (int s = 0; s < NSTAGE - 1; s++) {
        const int k0 = s << 6;
        #pragma unroll
        for (int i = 0; i < 4; i++) {
            cp_async16(asm_dst[s] + i * 8, Abase + k0 + i * 8, a_ok);
            cp_async16(bsm_dst[s] + i * 8, Bbase + (size_t)k0 * N + i * 8, true);
        }
        CP_COMMIT();
    }

    for (int kt = 0; kt < KT; kt++) {
        CP_WAIT1();
        __syncthreads();

        if (kt + NSTAGE - 1 < KT) {
            const int s  = (kt + NSTAGE - 1) % NSTAGE;
            const int k0 = (kt + NSTAGE - 1) << 6;
            #pragma unroll
            for (int i = 0; i < 4; i++) {
                cp_async16(asm_dst[s] + i * 8, Abase + k0 + i * 8, a_ok);
                cp_async16(bsm_dst[s] + i * 8, Bbase + (size_t)k0 * N + i * 8, true);
            }
        }
        CP_COMMIT();

        const __half* Ab = Asm + (kt % NSTAGE) * AS_STAGE;
        const __half* Bb = Bsm + (kt % NSTAGE) * BS_STAGE;

        #pragma unroll
        for (int ks = 0; ks < 4; ks++) {
            const int kk = ks << 4;
            uint32_t af[4][4];
            uint32_t bf[4][2];
            #pragma unroll
            for (int mt = 0; mt < 4; mt++) {
                const int r0 = wm + mt * 16;
                ldsm_x4(af[mt][0], af[mt][1], af[mt][2], af[mt][3],
                        Ab + (size_t)(r0 + l16) * APADH + kk + lhi);
            }
            #pragma unroll
            for (int pr = 0; pr < 2; pr++) {
                const int c0 = wn + pr * 16;
                ldsm_x4_trans(bf[pr * 2][0], bf[pr * 2][1], bf[pr * 2 + 1][0], bf[pr * 2 + 1][1],
                              Bb + (size_t)(kk + l16) * BPADH + c0 + lhi);
            }
            #pragma unroll
            for (int mt = 0; mt < 4; mt++)
                #pragma unroll
                for (int nt = 0; nt < 4; nt++)
                    mma_f16(acc[mt][nt][0], acc[mt][nt][1], acc[mt][nt][2], acc[mt][nt][3],
                            af[mt][0], af[mt][1], af[mt][2], af[mt][3],
                            bf[nt][0], bf[nt][1]);
        }
    }

    #pragma unroll
    for (int mt = 0; mt < 4; mt++) {
        const int r0 = bm + wm + mt * 16 + gid;
        const int r1 = r0 + 8;
        #pragma unroll
        for (int nt = 0; nt < 4; nt++) {
            const int c = bn + wn + nt * 8 + tig * 2;
            const float b0 = bias[c], b1 = bias[c + 1];
            float v0 = acc[mt][nt][0] + b0;
            float v1 = acc[mt][nt][1] + b1;
            float v2 = acc[mt][nt][2] + b0;
            float v3 = acc[mt][nt][3] + b1;
            if (relu) {
                v0 = fmaxf(v0, 0.f); v1 = fmaxf(v1, 0.f);
                v2 = fmaxf(v2, 0.f); v3 = fmaxf(v3, 0.f);
            }
            if (r0 < M) *(__half2*)(Cout + (size_t)r0 * N + c) = __floats2half2_rn(v0, v1);
            if (r1 < M) *(__half2*)(Cout + (size_t)r1 * N + c) = __floats2half2_rn(v2, v3);
        }
    }
}

// ---------------- multi-scale deformable attention (round-9 version) ----------------
__global__ __launch_bounds__(256) void deform_attn_kernel(
    const __half* __restrict__ voa, const float* __restrict__ ref,
    __half* __restrict__ out)
{
    const int gw = blockIdx.x * 8 + (threadIdx.x >> 5);
    if (gw >= MROWS * 4) return;
    const int lane = threadIdx.x & 31;
    const int hp = gw & 3;
    const int bn = gw >> 2;
    const int b  = bn / NQ;
    const int h  = hp * 2 + (lane >> 4);
    const int p  = lane & 15;
    const int lvl = p >> 2;

    const __half* offp = voa + (size_t)bn * CATN + 256 + h * 32;
    float ox = __half2float(offp[p * 2 + 0]);
    float oy = __half2float(offp[p * 2 + 1]);
    float logit = __half2float(voa[(size_t)bn * CATN + 512 + h * 16 + p]);

    float mx = logit;
    #pragma unroll
    for (int o = 8; o > 0; o >>= 1) mx = fmaxf(mx, __shfl_xor_sync(0xFFFFFFFFu, mx, o));
    float e = __expf(logit - mx);
    float ss = e;
    #pragma unroll
    for (int o = 8; o > 0; o >>= 1) ss += __shfl_xor_sync(0xFFFFFFFFu, ss, o);
    const float prob = e / ss;

    const int W = c_w[lvl], H = c_h[lvl], S = c_start[lvl];
    const float fw = (float)W, fh = (float)H;
    const float rx = ref[((size_t)bn * NLVL + lvl) * 2 + 0];
    const float ry = ref[((size_t)bn * NLVL + lvl) * 2 + 1];

    const float locx = rx + ox / fw;
    const float locy = ry + oy / fh;
    const float xs = locx * fw - 0.5f;
    const float ys = locy * fh - 0.5f;
    const float fxs = floorf(xs), fys = floorf(ys);
    const int x0 = (int)fxs, y0 = (int)fys;
    const float lx = xs - fxs, ly = ys - fys;
    const int x1 = x0 + 1, y1 = y0 + 1;

    const float vx0 = (x0 >= 0 && x0 < W) ? 1.f : 0.f;
    const float vx1 = (x1 >= 0 && x1 < W) ? 1.f : 0.f;
    const float vy0 = (y0 >= 0 && y0 < H) ? 1.f : 0.f;
    const float vy1 = (y1 >= 0 && y1 < H) ? 1.f : 0.f;

    float w00 = (1.f - lx) * (1.f - ly) * prob * vy0 * vx0;
    float w01 = lx * (1.f - ly) * prob * vy0 * vx1;
    float w10 = (1.f - lx) * ly * prob * vy1 * vx0;
    float w11 = lx * ly * prob * vy1 * vx1;

    const int x0c = min(max(x0, 0), W - 1);
    const int x1c = min(max(x1, 0), W - 1);
    const int y0c = min(max(y0, 0), H - 1);
    const int y1c = min(max(y1, 0), H - 1);

    int r00 = S + y0c * W + x0c;
    int r01 = S + y0c * W + x1c;
    int r10 = S + y1c * W + x0c;
    int r11 = S + y1c * W + x1c;

    const int l16 = lane & 15;
    const __half2* vbase = (const __half2*)(voa + (size_t)b * NQ * CATN + h * HDIM) + l16;
    const int ROWH2 = CATN / 2;

    float2 acc = make_float2(0.f, 0.f);

    #pragma unroll
    for (int q = 0; q < 16; q++) {
        const int   i00 = __shfl_sync(0xFFFFFFFFu, r00, q, 16);
        const int   i01 = __shfl_sync(0xFFFFFFFFu, r01, q, 16);
        const int   i10 = __shfl_sync(0xFFFFFFFFu, r10, q, 16);
        const int   i11 = __shfl_sync(0xFFFFFFFFu, r11, q, 16);
        const float a00 = __shfl_sync(0xFFFFFFFFu, w00, q, 16);
        const float a01 = __shfl_sync(0xFFFFFFFFu, w01, q, 16);
        const float a10 = __shfl_sync(0xFFFFFFFFu, w10, q, 16);
        const float a11 = __shfl_sync(0xFFFFFFFFu, w11, q, 16);

        const float2 f00 = __half22float2(vbase[(size_t)i00 * ROWH2]);
        const float2 f01 = __half22float2(vbase[(size_t)i01 * ROWH2]);
        const float2 f10 = __half22float2(vbase[(size_t)i10 * ROWH2]);
        const float2 f11 = __half22float2(vbase[(size_t)i11 * ROWH2]);

        acc.x += a00 * f00.x + a01 * f01.x + a10 * f10.x + a11 * f11.x;
        acc.y += a00 * f00.y + a01 * f01.y + a10 * f10.y + a11 * f11.y;
    }

    __half2* op = (__half2*)(out + (size_t)bn * E_ + h * HDIM) + l16;
    *op = __floats2half2_rn(acc.x, acc.y);
}

// ---------------- fused residual add + LayerNorm (warp per row, vectorized) ----------------
// x fp32 residual; r fp16 branch. Each lane owns contiguous cols [lane*8, lane*8+8):
// 2x LDG.128 (x), 1x LDG.128 (r half8), vector stores.
__global__ __launch_bounds__(256) void add_ln_kernel(
    const float* __restrict__ x, const __half* __restrict__ r,
    const float* __restrict__ gamma, const float* __restrict__ beta,
    float* __restrict__ out_f, __half* __restrict__ out_h, int M)
{
    int row = blockIdx.x * 8 + (threadIdx.x >> 5);
    if (row >= M) return;
    int lane = threadIdx.x & 31;
    const int c0 = lane * 8;

    const float4* xp = (const float4*)(x + (size_t)row * E_ + c0);
    const uint4   rv = *(const uint4*)(r + (size_t)row * E_ + c0);

    float vals[8];
    {
        float4 x0 = xp[0], x1 = xp[1];
        float2 h0 = __half22float2(*(const __half2*)&rv.x);
        float2 h1 = __half22float2(*(const __half2*)&rv.y);
        float2 h2 = __half22float2(*(const __half2*)&rv.z);
        float2 h3 = __half22float2(*(const __half2*)&rv.w);
        vals[0] = x0.x + h0.x; vals[1] = x0.y + h0.y;
        vals[2] = x0.z + h1.x; vals[3] = x0.w + h1.y;
        vals[4] = x1.x + h2.x; vals[5] = x1.y + h2.y;
        vals[6] = x1.z + h3.x; vals[7] = x1.w + h3.y;
    }

    float s = 0.f;
    #pragma unroll
    for (int i = 0; i < 8; i++) s += vals[i];
    #pragma unroll
    for (int o = 16; o > 0; o >>= 1) s += __shfl_xor_sync(0xFFFFFFFFu, s, o);
    float mean = s * (1.f / E_);

    float vs = 0.f;
    #pragma unroll
    for (int i = 0; i < 8; i++) {
        float d = vals[i] - mean;
        vs += d * d;
    }
    #pragma unroll
    for (int o = 16; o > 0; o >>= 1) vs += __shfl_xor_sync(0xFFFFFFFFu, vs, o);
    float inv = rsqrtf(vs * (1.f / E_) + EPS);

    const float4 g0 = *(const float4*)(gamma + c0);
    const float4 g1 = *(const float4*)(gamma + c0 + 4);
    const float4 b0 = *(const float4*)(beta  + c0);
    const float4 b1 = *(const float4*)(beta  + c0 + 4);

    float o0 = (vals[0] - mean) * inv * g0.x + b0.x;
    float o1 = (vals[1] - mean) * inv * g0.y + b0.y;
    float o2 = (vals[2] - mean) * inv * g0.z + b0.z;
    float o3 = (vals[3] - mean) * inv * g0.w + b0.w;
    float o4 = (vals[4] - mean) * inv * g1.x + b1.x;
    float o5 = (vals[5] - mean) * inv * g1.y + b1.y;
    float o6 = (vals[6] - mean) * inv * g1.z + b1.z;
    float o7 = (vals[7] - mean) * inv * g1.w + b1.w;

    float4* opf = (float4*)(out_f + (size_t)row * E_ + c0);
    opf[0] = make_float4(o0, o1, o2, o3);
    opf[1] = make_float4(o4, o5, o6, o7);

    if (out_h) {
        uint4 hv;
        __half2 t;
        t = __floats2half2_rn(o0, o1); hv.x = *(uint32_t*)&t;
        t = __floats2half2_rn(o2, o3); hv.y = *(uint32_t*)&t;
        t = __floats2half2_rn(o4, o5); hv.z = *(uint32_t*)&t;
        t = __floats2half2_rn(o6, o7); hv.w = *(uint32_t*)&t;
        *(uint4*)(out_h + (size_t)row * E_ + c0) = hv;
    }
}

// ---------------- launcher ----------------
static inline void run_gemm(const __half* A, const __half* W, const float* b,
                            __half* C, int M, int K, int Nc, int relu) {
    dim3 grid(Nc / TBN, (M + TBM - 1) / TBM);
    gemm_f16<<<grid, 256, GEMM_SMEM_BYTES>>>(A, W, b, C, M, K, Nc, relu);
}

extern "C" void kernel_launch(void* const* d_in, const int* in_sizes, int n_in,
                              void* d_out, int out_size) {
    const float* src  = (const float*)d_in[0];
    const float* ref  = (const float*)d_in[1];
    const float* Woff = (const float*)d_in[4];
    const float* boff = (const float*)d_in[5];
    const float* Waw  = (const float*)d_in[6];
    const float* baw  = (const float*)d_in[7];
    const float* Wv   = (const float*)d_in[8];
    const float* bv   = (const float*)d_in[9];
    const float* Wo   = (const float*)d_in[10];
    const float* bo   = (const float*)d_in[11];
    const float* ln1g = (const float*)d_in[12];
    const float* ln1b = (const float*)d_in[13];
    const float* Wf1  = (const float*)d_in[14];
    const float* bf1  = (const float*)d_in[15];
    const float* Wf2  = (const float*)d_in[16];
    const float* bf2  = (const float*)d_in[17];
    const float* ln2g = (const float*)d_in[18];
    const float* ln2b = (const float*)d_in[19];
    float* out = (float*)d_out;

    cudaFuncSetAttribute(gemm_f16, cudaFuncAttributeMaxDynamicSharedMemorySize, GEMM_SMEM_BYTES);

    float *px, *pbcat;
    __half *pxh, *pvoa, *psamp, *ptmph, *pffn, *pwcat, *pwo, *pwf1, *pwf2;
    cudaGetSymbolAddress((void**)&px,    g_x);
    cudaGetSymbolAddress((void**)&pxh,   g_xh);
    cudaGetSymbolAddress((void**)&pvoa,  g_voa);
    cudaGetSymbolAddress((void**)&psamp, g_samp);
    cudaGetSymbolAddress((void**)&ptmph, g_tmph);
    cudaGetSymbolAddress((void**)&pffn,  g_ffn);
    cudaGetSymbolAddress((void**)&pwcat, g_wcat);
    cudaGetSymbolAddress((void**)&pbcat, g_bcat);
    cudaGetSymbolAddress((void**)&pwo,   g_wo);
    cudaGetSymbolAddress((void**)&pwf1,  g_wf1);
    cudaGetSymbolAddress((void**)&pwf2,  g_wf2);

    const int M = MROWS;
    const int nElem = M * E_;

    src_copy_kernel<<<(nElem + 255) / 256, 256>>>(src, px, pxh, nElem);
    prep_weights_kernel<<<(PREP_TOTAL + 255) / 256, 256>>>(
        Wv, Woff, Waw, bv, boff, baw, Wo, Wf1, Wf2,
        pwcat, pbcat, pwo, pwf1, pwf2);

    const int dwarps = M * 4;
    const int dgrid  = (dwarps + 7) / 8;

    for (int layer = 0; layer < 6; layer++) {
        // fused projections: [v | off | aw-logits], fp16 out
        run_gemm(pxh, pwcat, pbcat, pvoa, M, E_, CATN, 0);

        deform_attn_kernel<<<dgrid, 256>>>(pvoa, ref, psamp);

        run_gemm(psamp, pwo, bo, ptmph, M, E_, E_, 0);                   // fp16 branch out
        add_ln_kernel<<<(M + 7) / 8, 256>>>(px, ptmph, ln1g, ln1b, px, pxh, M);

        run_gemm(pxh,  pwf1, bf1, pffn, M, E_, F_, 1);                   // relu, fp16 out
        run_gemm(pffn, pwf2, bf2, ptmph, M, F_, E_, 0);                  // fp16 branch out

        float* dst = (layer == 5) ? out : px;
        __half* dsth = (layer == 5) ? (__half*)nullptr : pxh;
        add_ln_kernel<<<(M + 7) / 8, 256>>>(px, ptmph, ln2g, ln2b, dst, dsth, M);
    }
}